// round 7
// baseline (speedup 1.0000x reference)
#include <cuda_runtime.h>
#include <cuda_bf16.h>
#include <math.h>
#include <stdint.h>

// Problem constants
#define Asz   384
#define Tsz   128
#define Bsz   1024
#define Lsz   50
#define G4    1536
#define BA    (Bsz*Asz)
#define OUTLD (Lsz*Asz)

// GEMM tiling
#define TM    128
#define TN    96
#define KC    64            // bf16 K elems per chunk (128B payload per row)
#define ROWB  144           // smem row stride bytes (128 payload + 16 pad)
#define NT    384           // 12 warps: 4(M) x 3(N), warp tile 32x32
#define NSTG  3
#define STAGE ((TM + TN) * ROWB)       // 32256 B
#define SMEMB (64 + NSTG * STAGE)      // 64B mbar header + stages
#define NROWS (TM + TN)                // 224 bulk copies per chunk
#define CHUNKB ((TM + TN) * 128)       // 28672 tx bytes per chunk

// ---------------------------------------------------------------------------
// Device scratch
// ---------------------------------------------------------------------------
__device__ __align__(128) __nv_bfloat16 g_Wcomb[3][G4][768]; // gate-interleaved rows: [x | h]
__device__ __align__(128) __nv_bfloat16 g_Wtag[G4][Tsz];     // gate-interleaved rows, tag slice
__device__ __align__(128) __nv_bfloat16 g_Wlb[Asz][Asz];
__device__ __align__(128) __nv_bfloat16 g_tagsb[Bsz][Tsz];
__device__ __align__(128) __nv_bfloat16 g_hb[3][2][BA];
__device__ __align__(128) __nv_bfloat16 g_prevb[2][BA];
__device__ __align__(128) float g_c[3][BA];
__device__ __align__(128) float g_tagbias[Bsz * G4];
__device__ __align__(128) float g_biasI[3][G4];

__device__ __forceinline__ float sigf(float x) { return 1.0f / (1.0f + __expf(-x)); }
__device__ __forceinline__ float tanhf_fast(float x) { return 2.0f / (1.0f + __expf(-2.0f * x)) - 1.0f; }

// ---------------------------------------------------------------------------
// PTX helpers
// ---------------------------------------------------------------------------
__device__ __forceinline__ uint32_t smem_u32(const void* p)
{
    uint32_t a;
    asm("{ .reg .u64 t; cvta.to.shared.u64 t, %1; cvt.u32.u64 %0, t; }" : "=r"(a) : "l"(p));
    return a;
}

__device__ __forceinline__ void ldsm_x4(uint32_t r[4], uint32_t addr)
{
    asm volatile("ldmatrix.sync.aligned.m8n8.x4.shared.b16 {%0,%1,%2,%3}, [%4];"
        : "=r"(r[0]), "=r"(r[1]), "=r"(r[2]), "=r"(r[3]) : "r"(addr));
}

__device__ __forceinline__ void mma_bf16(float c[4], const uint32_t a[4], const uint32_t b0, const uint32_t b1)
{
    asm volatile(
        "mma.sync.aligned.m16n8k16.row.col.f32.bf16.bf16.f32 "
        "{%0,%1,%2,%3},{%4,%5,%6,%7},{%8,%9},{%0,%1,%2,%3};"
        : "+f"(c[0]), "+f"(c[1]), "+f"(c[2]), "+f"(c[3])
        : "r"(a[0]), "r"(a[1]), "r"(a[2]), "r"(a[3]), "r"(b0), "r"(b1));
}

#define MBAR_INIT(a, n) asm volatile("mbarrier.init.shared.b64 [%0], %1;" :: "r"(a), "r"(n) : "memory")

__device__ __forceinline__ void mbar_arrive_tx(uint32_t mb, uint32_t tx)
{
    asm volatile("mbarrier.arrive.expect_tx.shared.b64 _, [%0], %1;" :: "r"(mb), "r"(tx) : "memory");
}

__device__ __forceinline__ void bulk_cp(uint32_t dst, const void* src, uint32_t bytes, uint32_t mb)
{
    asm volatile(
        "cp.async.bulk.shared::cluster.global.mbarrier::complete_tx::bytes [%0], [%1], %2, [%3];"
        :: "r"(dst), "l"(src), "r"(bytes), "r"(mb) : "memory");
}

__device__ __forceinline__ void mbar_wait(uint32_t mbar, uint32_t parity)
{
    asm volatile(
        "{\n\t.reg .pred P;\n"
        "WL%=:\n\t"
        "mbarrier.try_wait.parity.acquire.cta.shared::cta.b64 P, [%0], %1, 0x989680;\n\t"
        "@P bra WD%=;\n\t"
        "bra WL%=;\n"
        "WD%=:\n\t}"
        :: "r"(mbar), "r"(parity) : "memory");
}

// ---------------------------------------------------------------------------
// Prep: convert/interleave weights, biases, tags; init states + out[:,0,:]
// ---------------------------------------------------------------------------
__global__ void prep_kernel(
    const float* __restrict__ tags,
    const float* __restrict__ Wih0, const float* __restrict__ Whh0,
    const float* __restrict__ bih0, const float* __restrict__ bhh0,
    const float* __restrict__ Wih1, const float* __restrict__ Whh1,
    const float* __restrict__ bih1, const float* __restrict__ bhh1,
    const float* __restrict__ Wih2, const float* __restrict__ Whh2,
    const float* __restrict__ bih2, const float* __restrict__ bhh2,
    const float* __restrict__ Wl,
    float* __restrict__ out)
{
    const int gid = blockIdx.x * blockDim.x + threadIdx.x;
    const int GT  = gridDim.x * blockDim.x;

    for (int idx = gid; idx < BA; idx += GT) {
        int m = idx / Asz, n = idx - m * Asz;
        float v = (n == 1) ? 1.0f : 0.0f;   // START = 1
        out[(size_t)m * OUTLD + n] = v;
        g_prevb[0][idx] = __float2bfloat16_rn(v);
        #pragma unroll
        for (int l = 0; l < 3; l++) {
            g_hb[l][0][idx] = __float2bfloat16_rn(0.0f);
            g_c[l][idx] = 0.0f;
        }
    }
    for (int idx = gid; idx < Bsz * Tsz; idx += GT)
        ((__nv_bfloat16*)g_tagsb)[idx] = __float2bfloat16_rn(tags[idx]);
    {
        const float* WihA[3] = {Wih0, Wih1, Wih2};
        const float* WhhA[3] = {Whh0, Whh1, Whh2};
        for (int idx = gid; idx < 3 * G4 * 768; idx += GT) {
            int l   = idx / (G4 * 768);
            int rem = idx - l * (G4 * 768);
            int rp  = rem / 768, k = rem - rp * 768;
            int lr  = (rp & 3) * Asz + (rp >> 2);
            float v;
            if (k < Asz) v = (l == 0) ? WihA[0][(size_t)lr * (Asz + Tsz) + k]
                                      : WihA[l][(size_t)lr * Asz + k];
            else         v = WhhA[l][(size_t)lr * Asz + (k - Asz)];
            ((__nv_bfloat16*)g_Wcomb)[idx] = __float2bfloat16_rn(v);
        }
    }
    for (int idx = gid; idx < G4 * Tsz; idx += GT) {
        int rp = idx / Tsz, k = idx - rp * Tsz;
        int lr = (rp & 3) * Asz + (rp >> 2);
        ((__nv_bfloat16*)g_Wtag)[idx] = __float2bfloat16_rn(Wih0[(size_t)lr * (Asz + Tsz) + Asz + k]);
    }
    for (int idx = gid; idx < Asz * Asz; idx += GT)
        ((__nv_bfloat16*)g_Wlb)[idx] = __float2bfloat16_rn(Wl[idx]);
    {
        const float* bihA[3] = {bih0, bih1, bih2};
        const float* bhhA[3] = {bhh0, bhh1, bhh2};
        for (int idx = gid; idx < 3 * G4; idx += GT) {
            int l = idx / G4, rp = idx - l * G4;
            int lr = (rp & 3) * Asz + (rp >> 2);
            g_biasI[l][rp] = bihA[l][lr] + bhhA[l][lr];
        }
    }
}

// ---------------------------------------------------------------------------
// bf16 mma.sync GEMM, 128x96 CTA tile, 12 warps (32x32 warp tiles),
// 3-stage pipeline with per-row cp.async.bulk + mbarrier complete_tx.
// MODE 0: Cf = acc + biasv            (tagbias build, interleaved cols)
// MODE 1: fused LSTM cell (interleaved gate cols) -> h bf16, c fp32
// MODE 2: sigmoid head -> prevb bf16 + outp fp32
// ---------------------------------------------------------------------------
template<int MODE>
__global__ void __launch_bounds__(NT) gemm_kernel(
    const __nv_bfloat16* __restrict__ X, int ldx, int Kx,
    const __nv_bfloat16* __restrict__ H,                 // nullable; lda=Asz, K=Asz
    const __nv_bfloat16* __restrict__ W, int ldw,
    const float* __restrict__ biasv,
    const float* __restrict__ bmat,
    float* __restrict__ Cf,
    __nv_bfloat16* __restrict__ hout, float* __restrict__ cstate,
    __nv_bfloat16* __restrict__ prevb, float* __restrict__ outp)
{
    extern __shared__ __align__(128) unsigned char dsm[];

    const int m0   = blockIdx.y * TM;
    const int n0   = blockIdx.x * TN;
    const int tid  = threadIdx.x;
    const int warp = tid >> 5;
    const int lane = tid & 31;
    const int wmi  = warp / 3;           // 0..3 (M)
    const int wni  = warp % 3;           // 0..2 (N)
    const int g    = lane >> 2;
    const int tg   = lane & 3;
    const int mi   = lane >> 3;          // ldmatrix matrix id 0..3
    const int lr   = lane & 7;

    const uint32_t sb = smem_u32(dsm);   // [0,64): 3 mbarriers; [64,...): stages

    if (tid == 0) {
        MBAR_INIT(sb + 0,  NROWS);
        MBAR_INIT(sb + 8,  NROWS);
        MBAR_INIT(sb + 16, NROWS);
    }
    __syncthreads();

    float acc[2][4][4];
    #pragma unroll
    for (int ms = 0; ms < 2; ms++)
        #pragma unroll
        for (int ns = 0; ns < 4; ns++)
            #pragma unroll
            for (int r = 0; r < 4; r++) acc[ms][ns][r] = 0.0f;

    const int ncx = Kx / KC;
    const int nc  = ncx + ((H != nullptr) ? (Asz / KC) : 0);

    auto fill = [&](int c) {
        if (tid >= NROWS) return;
        const int buf = c % NSTG;
        const uint32_t mb = sb + buf * 8;
        const uint32_t sA = sb + 64 + buf * STAGE;
        const __nv_bfloat16* Asrc;
        int la, kb;
        if (c < ncx) { Asrc = X; la = ldx; kb = c * KC; }
        else         { Asrc = H; la = Asz; kb = (c - ncx) * KC; }
        const void* src;
        uint32_t dst;
        if (tid < TM) {
            src = Asrc + (size_t)(m0 + tid) * la + kb;
            dst = sA + tid * ROWB;
        } else {
            const int row = tid - TM;
            src = W + (size_t)(n0 + row) * ldw + c * KC;
            dst = sA + (TM + row) * ROWB;
        }
        mbar_arrive_tx(mb, 128u);
        bulk_cp(dst, src, 128u, mb);
    };

    auto compute = [&](int buf) {
        const uint32_t sA = sb + 64 + buf * STAGE;
        const uint32_t sW = sA + TM * ROWB;
        // ldmatrix lane base addresses (matrix order [r0k0, r8k0, r0k8, r8k8])
        const uint32_t aB = sA + (wmi * 32 + (mi & 1) * 8 + lr) * ROWB + (mi >> 1) * 16;
        const uint32_t wB = sW + (wni * 32 + (mi & 1) * 8 + lr) * ROWB + (mi >> 1) * 16;
        #pragma unroll
        for (int kt = 0; kt < 4; kt++) {       // 4 x k16 per chunk
            uint32_t a0[4], a1[4], b0[4], b1[4];
            ldsm_x4(a0, aB + kt * 32);
            ldsm_x4(a1, aB + 16 * ROWB + kt * 32);
            ldsm_x4(b0, wB + kt * 32);
            ldsm_x4(b1, wB + 16 * ROWB + kt * 32);
            mma_bf16(acc[0][0], a0, b0[0], b0[2]);
            mma_bf16(acc[1][0], a1, b0[0], b0[2]);
            mma_bf16(acc[0][1], a0, b0[1], b0[3]);
            mma_bf16(acc[1][1], a1, b0[1], b0[3]);
            mma_bf16(acc[0][2], a0, b1[0], b1[2]);
            mma_bf16(acc[1][2], a1, b1[0], b1[2]);
            mma_bf16(acc[0][3], a0, b1[1], b1[3]);
            mma_bf16(acc[1][3], a1, b1[1], b1[3]);
        }
    };

    fill(0);
    if (nc > 1) fill(1);
    for (int c = 0; c < nc; c++) {
        __syncthreads();                 // all warps done with compute(c-1) -> its buffer may be refilled
        if (c + 2 < nc) fill(c + 2);
        mbar_wait(sb + (c % NSTG) * 8, (uint32_t)((c / NSTG) & 1));
        compute(c % NSTG);
    }

    // ---- Epilogue ----
    #pragma unroll
    for (int ms = 0; ms < 2; ms++) {
        const int r = m0 + wmi * 32 + ms * 16 + g;
        #pragma unroll
        for (int ns = 0; ns < 4; ns++) {
            const int c0 = n0 + wni * 32 + ns * 8 + 2 * tg;
            float v00 = acc[ms][ns][0], v01 = acc[ms][ns][1];
            float v10 = acc[ms][ns][2], v11 = acc[ms][ns][3];
            if (biasv) {
                float bb0 = biasv[c0], bb1 = biasv[c0 + 1];
                v00 += bb0; v01 += bb1; v10 += bb0; v11 += bb1;
            }
            if (MODE == 0) {
                Cf[(size_t)r * G4 + c0]           = v00;
                Cf[(size_t)r * G4 + c0 + 1]       = v01;
                Cf[(size_t)(r + 8) * G4 + c0]     = v10;
                Cf[(size_t)(r + 8) * G4 + c0 + 1] = v11;
            } else if (MODE == 1) {
                if (bmat) {
                    v00 += bmat[(size_t)r * G4 + c0];
                    v01 += bmat[(size_t)r * G4 + c0 + 1];
                    v10 += bmat[(size_t)(r + 8) * G4 + c0];
                    v11 += bmat[(size_t)(r + 8) * G4 + c0 + 1];
                }
                // interleaved cols: even tg lanes hold (i,f); xor-1 partner holds (g,o)
                float p00 = __shfl_xor_sync(0xffffffffu, v00, 1);
                float p01 = __shfl_xor_sync(0xffffffffu, v01, 1);
                float p10 = __shfl_xor_sync(0xffffffffu, v10, 1);
                float p11 = __shfl_xor_sync(0xffffffffu, v11, 1);
                if ((tg & 1) == 0) {
                    const int n = c0 >> 2;
                    {
                        float cold = cstate[(size_t)r * Asz + n];
                        float c2 = sigf(v01) * cold + sigf(v00) * tanhf_fast(p00);
                        cstate[(size_t)r * Asz + n] = c2;
                        hout[(size_t)r * Asz + n] = __float2bfloat16_rn(sigf(p01) * tanhf_fast(c2));
                    }
                    {
                        float cold = cstate[(size_t)(r + 8) * Asz + n];
                        float c2 = sigf(v11) * cold + sigf(v10) * tanhf_fast(p10);
                        cstate[(size_t)(r + 8) * Asz + n] = c2;
                        hout[(size_t)(r + 8) * Asz + n] = __float2bfloat16_rn(sigf(p11) * tanhf_fast(c2));
                    }
                }
            } else { // MODE 2
                v00 = sigf(v00); v01 = sigf(v01); v10 = sigf(v10); v11 = sigf(v11);
                prevb[(size_t)r * Asz + c0]           = __float2bfloat16_rn(v00);
                prevb[(size_t)r * Asz + c0 + 1]       = __float2bfloat16_rn(v01);
                prevb[(size_t)(r + 8) * Asz + c0]     = __float2bfloat16_rn(v10);
                prevb[(size_t)(r + 8) * Asz + c0 + 1] = __float2bfloat16_rn(v11);
                outp[(size_t)r * OUTLD + c0]           = v00;
                outp[(size_t)r * OUTLD + c0 + 1]       = v01;
                outp[(size_t)(r + 8) * OUTLD + c0]     = v10;
                outp[(size_t)(r + 8) * OUTLD + c0 + 1] = v11;
            }
        }
    }
}

// ---------------------------------------------------------------------------
// Launch sequence (graph-capturable: kernel launches only)
// ---------------------------------------------------------------------------
extern "C" void kernel_launch(void* const* d_in, const int* in_sizes, int n_in,
                              void* d_out, int out_size)
{
    const float* tags = (const float*)d_in[2];
    const float* Wih0 = (const float*)d_in[4];
    const float* Whh0 = (const float*)d_in[5];
    const float* bih0 = (const float*)d_in[6];
    const float* bhh0 = (const float*)d_in[7];
    const float* Wih1 = (const float*)d_in[8];
    const float* Whh1 = (const float*)d_in[9];
    const float* bih1 = (const float*)d_in[10];
    const float* bhh1 = (const float*)d_in[11];
    const float* Wih2 = (const float*)d_in[12];
    const float* Whh2 = (const float*)d_in[13];
    const float* bih2 = (const float*)d_in[14];
    const float* bhh2 = (const float*)d_in[15];
    const float* Wl   = (const float*)d_in[16];
    const float* bl   = (const float*)d_in[17];
    float* out = (float*)d_out;

    __nv_bfloat16 *p_tagsb, *p_Wtag, *p_Wcomb, *p_Wlb, *p_hb, *p_prevb;
    float *p_tb, *p_c, *p_bI;
    cudaGetSymbolAddress((void**)&p_tagsb, g_tagsb);
    cudaGetSymbolAddress((void**)&p_Wtag,  g_Wtag);
    cudaGetSymbolAddress((void**)&p_Wcomb, g_Wcomb);
    cudaGetSymbolAddress((void**)&p_Wlb,   g_Wlb);
    cudaGetSymbolAddress((void**)&p_hb,    g_hb);
    cudaGetSymbolAddress((void**)&p_prevb, g_prevb);
    cudaGetSymbolAddress((void**)&p_tb,    g_tagbias);
    cudaGetSymbolAddress((void**)&p_c,     g_c);
    cudaGetSymbolAddress((void**)&p_bI,    g_biasI);

    auto hb   = [&](int l, int pp) { return p_hb + ((size_t)l * 2 + pp) * BA; };
    auto prv_ = [&](int pp)        { return p_prevb + (size_t)pp * BA; };

    cudaFuncSetAttribute(gemm_kernel<0>, cudaFuncAttributeMaxDynamicSharedMemorySize, SMEMB);
    cudaFuncSetAttribute(gemm_kernel<1>, cudaFuncAttributeMaxDynamicSharedMemorySize, SMEMB);
    cudaFuncSetAttribute(gemm_kernel<2>, cudaFuncAttributeMaxDynamicSharedMemorySize, SMEMB);

    const dim3 gridFull(G4 / TN, Bsz / TM);   // (16, 8) = 128 CTAs
    const dim3 gridHead(Asz / TN, Bsz / TM);  // (4, 8)  = 32 CTAs

    // 1) prep
    prep_kernel<<<1024, 256>>>(tags, Wih0, Whh0, bih0, bhh0,
                               Wih1, Whh1, bih1, bhh1,
                               Wih2, Whh2, bih2, bhh2, Wl, out);

    // 2) tagbias = tags @ Wtag^T + biasI[0]
    gemm_kernel<0><<<gridFull, NT, SMEMB>>>(p_tagsb, Tsz, Tsz, nullptr,
                                            p_Wtag, Tsz,
                                            p_bI, nullptr,
                                            p_tb, nullptr, nullptr, nullptr, nullptr);

    // 3) 49 recurrent steps
    for (int t = 1; t < Lsz; t++) {
        const int cur = t & 1, prv = cur ^ 1;

        gemm_kernel<1><<<gridFull, NT, SMEMB>>>(prv_(prv), Asz, Asz, hb(0, prv),
                                                p_Wcomb + 0 * (size_t)G4 * 768, 768,
                                                nullptr, p_tb,
                                                nullptr, hb(0, cur), p_c + 0 * BA,
                                                nullptr, nullptr);

        gemm_kernel<1><<<gridFull, NT, SMEMB>>>(hb(0, cur), Asz, Asz, hb(1, prv),
                                                p_Wcomb + 1 * (size_t)G4 * 768, 768,
                                                p_bI + G4, nullptr,
                                                nullptr, hb(1, cur), p_c + 1 * BA,
                                                nullptr, nullptr);

        gemm_kernel<1><<<gridFull, NT, SMEMB>>>(hb(1, cur), Asz, Asz, hb(2, prv),
                                                p_Wcomb + 2 * (size_t)G4 * 768, 768,
                                                p_bI + 2 * G4, nullptr,
                                                nullptr, hb(2, cur), p_c + 2 * BA,
                                                nullptr, nullptr);

        gemm_kernel<2><<<gridHead, NT, SMEMB>>>(hb(2, cur), Asz, Asz, nullptr,
                                                p_Wlb, Asz,
                                                bl, nullptr,
                                                nullptr, nullptr, nullptr,
                                                prv_(cur), out + (size_t)t * Asz);
    }
}

// round 8
// speedup vs baseline: 1.3297x; 1.3297x over previous
#include <cuda_runtime.h>
#include <cuda_bf16.h>
#include <math.h>
#include <stdint.h>

// Problem constants
#define Asz   384
#define Tsz   128
#define Bsz   1024
#define Lsz   50
#define G4    1536
#define BA    (Bsz*Asz)
#define OUTLD (Lsz*Asz)

// GEMM tiling
#define TM    64
#define TN    96
#define KC    64            // bf16 K elems per chunk (128B payload per row)
#define ROWB  144           // smem row stride bytes (128 payload + 16 pad)
#define NT    192           // 6 warps: 2(M) x 3(N), warp tile 32x32
#define NSTG  3
#define STAGE ((TM + TN) * ROWB)       // 23040 B
#define SMEMB (NSTG * STAGE)           // 69120 B  (x2 CTAs = 138240 < 228KB)

// ---------------------------------------------------------------------------
// Device scratch
// ---------------------------------------------------------------------------
__device__ __align__(128) __nv_bfloat16 g_Wcomb[3][G4][768]; // gate-interleaved rows: [x | h]
__device__ __align__(128) __nv_bfloat16 g_Wtag[G4][Tsz];     // gate-interleaved rows, tag slice
__device__ __align__(128) __nv_bfloat16 g_Wlb[Asz][Asz];
__device__ __align__(128) __nv_bfloat16 g_tagsb[Bsz][Tsz];
__device__ __align__(128) __nv_bfloat16 g_hb[3][2][BA];
__device__ __align__(128) __nv_bfloat16 g_prevb[2][BA];
__device__ __align__(128) float g_c[3][BA];
__device__ __align__(128) float g_tagbias[Bsz * G4];
__device__ __align__(128) float g_biasI[3][G4];

__device__ __forceinline__ float sigf(float x) { return 1.0f / (1.0f + __expf(-x)); }
__device__ __forceinline__ float tanhf_fast(float x) { return 2.0f / (1.0f + __expf(-2.0f * x)) - 1.0f; }

// ---------------------------------------------------------------------------
// PTX helpers
// ---------------------------------------------------------------------------
__device__ __forceinline__ uint32_t smem_u32(const void* p)
{
    uint32_t a;
    asm("{ .reg .u64 t; cvta.to.shared.u64 t, %1; cvt.u32.u64 %0, t; }" : "=r"(a) : "l"(p));
    return a;
}

__device__ __forceinline__ void cpa16(uint32_t s, const void* g)
{
    asm volatile("cp.async.cg.shared.global [%0], [%1], 16;" :: "r"(s), "l"(g));
}
#define CP_COMMIT()  asm volatile("cp.async.commit_group;")
template<int N>
__device__ __forceinline__ void cp_wait() { asm volatile("cp.async.wait_group %0;" :: "n"(N) : "memory"); }

__device__ __forceinline__ void ldsm_x4(uint32_t r[4], uint32_t addr)
{
    asm volatile("ldmatrix.sync.aligned.m8n8.x4.shared.b16 {%0,%1,%2,%3}, [%4];"
        : "=r"(r[0]), "=r"(r[1]), "=r"(r[2]), "=r"(r[3]) : "r"(addr));
}

__device__ __forceinline__ void mma_bf16(float c[4], const uint32_t a[4], const uint32_t b0, const uint32_t b1)
{
    asm volatile(
        "mma.sync.aligned.m16n8k16.row.col.f32.bf16.bf16.f32 "
        "{%0,%1,%2,%3},{%4,%5,%6,%7},{%8,%9},{%0,%1,%2,%3};"
        : "+f"(c[0]), "+f"(c[1]), "+f"(c[2]), "+f"(c[3])
        : "r"(a[0]), "r"(a[1]), "r"(a[2]), "r"(a[3]), "r"(b0), "r"(b1));
}

// ---------------------------------------------------------------------------
// Prep: convert/interleave weights, biases, tags; init states + out[:,0,:]
// ---------------------------------------------------------------------------
__global__ void prep_kernel(
    const float* __restrict__ tags,
    const float* __restrict__ Wih0, const float* __restrict__ Whh0,
    const float* __restrict__ bih0, const float* __restrict__ bhh0,
    const float* __restrict__ Wih1, const float* __restrict__ Whh1,
    const float* __restrict__ bih1, const float* __restrict__ bhh1,
    const float* __restrict__ Wih2, const float* __restrict__ Whh2,
    const float* __restrict__ bih2, const float* __restrict__ bhh2,
    const float* __restrict__ Wl,
    float* __restrict__ out)
{
    const int gid = blockIdx.x * blockDim.x + threadIdx.x;
    const int GT  = gridDim.x * blockDim.x;

    for (int idx = gid; idx < BA; idx += GT) {
        int m = idx / Asz, n = idx - m * Asz;
        float v = (n == 1) ? 1.0f : 0.0f;   // START = 1
        out[(size_t)m * OUTLD + n] = v;
        g_prevb[0][idx] = __float2bfloat16_rn(v);
        #pragma unroll
        for (int l = 0; l < 3; l++) {
            g_hb[l][0][idx] = __float2bfloat16_rn(0.0f);
            g_c[l][idx] = 0.0f;
        }
    }
    for (int idx = gid; idx < Bsz * Tsz; idx += GT)
        ((__nv_bfloat16*)g_tagsb)[idx] = __float2bfloat16_rn(tags[idx]);
    {
        const float* WihA[3] = {Wih0, Wih1, Wih2};
        const float* WhhA[3] = {Whh0, Whh1, Whh2};
        for (int idx = gid; idx < 3 * G4 * 768; idx += GT) {
            int l   = idx / (G4 * 768);
            int rem = idx - l * (G4 * 768);
            int rp  = rem / 768, k = rem - rp * 768;
            int lr  = (rp & 3) * Asz + (rp >> 2);
            float v;
            if (k < Asz) v = (l == 0) ? WihA[0][(size_t)lr * (Asz + Tsz) + k]
                                      : WihA[l][(size_t)lr * Asz + k];
            else         v = WhhA[l][(size_t)lr * Asz + (k - Asz)];
            ((__nv_bfloat16*)g_Wcomb)[idx] = __float2bfloat16_rn(v);
        }
    }
    for (int idx = gid; idx < G4 * Tsz; idx += GT) {
        int rp = idx / Tsz, k = idx - rp * Tsz;
        int lr = (rp & 3) * Asz + (rp >> 2);
        ((__nv_bfloat16*)g_Wtag)[idx] = __float2bfloat16_rn(Wih0[(size_t)lr * (Asz + Tsz) + Asz + k]);
    }
    for (int idx = gid; idx < Asz * Asz; idx += GT)
        ((__nv_bfloat16*)g_Wlb)[idx] = __float2bfloat16_rn(Wl[idx]);
    {
        const float* bihA[3] = {bih0, bih1, bih2};
        const float* bhhA[3] = {bhh0, bhh1, bhh2};
        for (int idx = gid; idx < 3 * G4; idx += GT) {
            int l = idx / G4, rp = idx - l * G4;
            int lr = (rp & 3) * Asz + (rp >> 2);
            g_biasI[l][rp] = bihA[l][lr] + bhhA[l][lr];
        }
    }
}

// ---------------------------------------------------------------------------
// bf16 mma.sync GEMM, 64x96 CTA tile, 6 warps (32x32 warp tiles),
// 2 CTAs/SM, 3-stage cp.async pipeline, ldmatrix + fragment double-buffer.
// MODE 0: Cf = acc + biasv            (tagbias build, interleaved cols)
// MODE 1: fused LSTM cell (interleaved gate cols) -> h bf16, c fp32
// MODE 2: sigmoid head -> prevb bf16 + outp fp32
// ---------------------------------------------------------------------------
template<int MODE>
__global__ void __launch_bounds__(NT, 2) gemm_kernel(
    const __nv_bfloat16* __restrict__ X, int ldx, int Kx,
    const __nv_bfloat16* __restrict__ H,                 // nullable; lda=Asz, K=Asz
    const __nv_bfloat16* __restrict__ W, int ldw,
    const float* __restrict__ biasv,
    const float* __restrict__ bmat,
    float* __restrict__ Cf,
    __nv_bfloat16* __restrict__ hout, float* __restrict__ cstate,
    __nv_bfloat16* __restrict__ prevb, float* __restrict__ outp)
{
    extern __shared__ __align__(128) unsigned char dsm[];

    const int m0   = blockIdx.y * TM;
    const int n0   = blockIdx.x * TN;
    const int tid  = threadIdx.x;
    const int warp = tid >> 5;
    const int lane = tid & 31;
    const int wmi  = warp / 3;           // 0..1 (M)
    const int wni  = warp % 3;           // 0..2 (N)
    const int g    = lane >> 2;
    const int tg   = lane & 3;
    const int mi   = lane >> 3;          // ldmatrix matrix id 0..3
    const int lr   = lane & 7;

    const uint32_t sb = smem_u32(dsm);

    float acc[2][4][4];
    #pragma unroll
    for (int ms = 0; ms < 2; ms++)
        #pragma unroll
        for (int ns = 0; ns < 4; ns++)
            #pragma unroll
            for (int r = 0; r < 4; r++) acc[ms][ns][r] = 0.0f;

    const int ncx = Kx / KC;
    const int nc  = ncx + ((H != nullptr) ? (Asz / KC) : 0);

    auto fill = [&](int c) {
        const int buf = c % NSTG;
        const __nv_bfloat16* Asrc;
        int la, kb;
        if (c < ncx) { Asrc = X; la = ldx; kb = c * KC; }
        else         { Asrc = H; la = Asz; kb = (c - ncx) * KC; }
        const uint32_t sA = sb + buf * STAGE;
        const uint32_t sW = sA + TM * ROWB;
        // A: 64 rows x 8 segs = 512; W: 96 rows x 8 segs = 768; total 1280
        #pragma unroll
        for (int i = 0; i < 7; i++) {
            int f = tid + i * NT;
            if (f < (TM + TN) * 8) {
                int row = f >> 3, seg = f & 7;
                if (row < TM) {
                    cpa16(sA + row * ROWB + seg * 16,
                          Asrc + (size_t)(m0 + row) * la + kb + seg * 8);
                } else {
                    int wr = row - TM;
                    cpa16(sW + wr * ROWB + seg * 16,
                          W + (size_t)(n0 + wr) * ldw + c * KC + seg * 8);
                }
            }
        }
        CP_COMMIT();
    };

    auto compute = [&](int buf) {
        const uint32_t sA = sb + buf * STAGE;
        const uint32_t sW = sA + TM * ROWB;
        // ldmatrix lane base addresses (matrix order [r0k0, r8k0, r0k8, r8k8])
        const uint32_t aB = sA + (wmi * 32 + (mi & 1) * 8 + lr) * ROWB + (mi >> 1) * 16;
        const uint32_t wB = sW + (wni * 32 + (mi & 1) * 8 + lr) * ROWB + (mi >> 1) * 16;

        uint32_t a0[2][4], a1[2][4], b0[2][4], b1[2][4];
        ldsm_x4(a0[0], aB);
        ldsm_x4(a1[0], aB + 16 * ROWB);
        ldsm_x4(b0[0], wB);
        ldsm_x4(b1[0], wB + 16 * ROWB);
        #pragma unroll
        for (int kt = 0; kt < 4; kt++) {       // 4 x k16 per chunk
            const int cu = kt & 1, nx = cu ^ 1;
            if (kt < 3) {
                ldsm_x4(a0[nx], aB + (kt + 1) * 32);
                ldsm_x4(a1[nx], aB + 16 * ROWB + (kt + 1) * 32);
                ldsm_x4(b0[nx], wB + (kt + 1) * 32);
                ldsm_x4(b1[nx], wB + 16 * ROWB + (kt + 1) * 32);
            }
            mma_bf16(acc[0][0], a0[cu], b0[cu][0], b0[cu][2]);
            mma_bf16(acc[1][0], a1[cu], b0[cu][0], b0[cu][2]);
            mma_bf16(acc[0][1], a0[cu], b0[cu][1], b0[cu][3]);
            mma_bf16(acc[1][1], a1[cu], b0[cu][1], b0[cu][3]);
            mma_bf16(acc[0][2], a0[cu], b1[cu][0], b1[cu][2]);
            mma_bf16(acc[1][2], a1[cu], b1[cu][0], b1[cu][2]);
            mma_bf16(acc[0][3], a0[cu], b1[cu][1], b1[cu][3]);
            mma_bf16(acc[1][3], a1[cu], b1[cu][1], b1[cu][3]);
        }
    };

    fill(0);
    if (nc > 1) fill(1);
    for (int c = 0; c < nc; c++) {
        if (c + 1 < nc) cp_wait<1>(); else cp_wait<0>();
        __syncthreads();
        if (c + 2 < nc) fill(c + 2);
        compute(c % NSTG);
    }

    // ---- Epilogue ----
    #pragma unroll
    for (int ms = 0; ms < 2; ms++) {
        const int r = m0 + wmi * 32 + ms * 16 + g;
        #pragma unroll
        for (int ns = 0; ns < 4; ns++) {
            const int c0 = n0 + wni * 32 + ns * 8 + 2 * tg;
            float v00 = acc[ms][ns][0], v01 = acc[ms][ns][1];
            float v10 = acc[ms][ns][2], v11 = acc[ms][ns][3];
            if (biasv) {
                float bb0 = biasv[c0], bb1 = biasv[c0 + 1];
                v00 += bb0; v01 += bb1; v10 += bb0; v11 += bb1;
            }
            if (MODE == 0) {
                Cf[(size_t)r * G4 + c0]           = v00;
                Cf[(size_t)r * G4 + c0 + 1]       = v01;
                Cf[(size_t)(r + 8) * G4 + c0]     = v10;
                Cf[(size_t)(r + 8) * G4 + c0 + 1] = v11;
            } else if (MODE == 1) {
                if (bmat) {
                    v00 += bmat[(size_t)r * G4 + c0];
                    v01 += bmat[(size_t)r * G4 + c0 + 1];
                    v10 += bmat[(size_t)(r + 8) * G4 + c0];
                    v11 += bmat[(size_t)(r + 8) * G4 + c0 + 1];
                }
                // interleaved cols: even tg lanes hold (i,f); xor-1 partner holds (g,o)
                float p00 = __shfl_xor_sync(0xffffffffu, v00, 1);
                float p01 = __shfl_xor_sync(0xffffffffu, v01, 1);
                float p10 = __shfl_xor_sync(0xffffffffu, v10, 1);
                float p11 = __shfl_xor_sync(0xffffffffu, v11, 1);
                if ((tg & 1) == 0) {
                    const int n = c0 >> 2;
                    {
                        float cold = cstate[(size_t)r * Asz + n];
                        float c2 = sigf(v01) * cold + sigf(v00) * tanhf_fast(p00);
                        cstate[(size_t)r * Asz + n] = c2;
                        hout[(size_t)r * Asz + n] = __float2bfloat16_rn(sigf(p01) * tanhf_fast(c2));
                    }
                    {
                        float cold = cstate[(size_t)(r + 8) * Asz + n];
                        float c2 = sigf(v11) * cold + sigf(v10) * tanhf_fast(p10);
                        cstate[(size_t)(r + 8) * Asz + n] = c2;
                        hout[(size_t)(r + 8) * Asz + n] = __float2bfloat16_rn(sigf(p11) * tanhf_fast(c2));
                    }
                }
            } else { // MODE 2
                v00 = sigf(v00); v01 = sigf(v01); v10 = sigf(v10); v11 = sigf(v11);
                prevb[(size_t)r * Asz + c0]           = __float2bfloat16_rn(v00);
                prevb[(size_t)r * Asz + c0 + 1]       = __float2bfloat16_rn(v01);
                prevb[(size_t)(r + 8) * Asz + c0]     = __float2bfloat16_rn(v10);
                prevb[(size_t)(r + 8) * Asz + c0 + 1] = __float2bfloat16_rn(v11);
                outp[(size_t)r * OUTLD + c0]           = v00;
                outp[(size_t)r * OUTLD + c0 + 1]       = v01;
                outp[(size_t)(r + 8) * OUTLD + c0]     = v10;
                outp[(size_t)(r + 8) * OUTLD + c0 + 1] = v11;
            }
        }
    }
}

// ---------------------------------------------------------------------------
// Launch sequence (graph-capturable: kernel launches only)
// ---------------------------------------------------------------------------
extern "C" void kernel_launch(void* const* d_in, const int* in_sizes, int n_in,
                              void* d_out, int out_size)
{
    const float* tags = (const float*)d_in[2];
    const float* Wih0 = (const float*)d_in[4];
    const float* Whh0 = (const float*)d_in[5];
    const float* bih0 = (const float*)d_in[6];
    const float* bhh0 = (const float*)d_in[7];
    const float* Wih1 = (const float*)d_in[8];
    const float* Whh1 = (const float*)d_in[9];
    const float* bih1 = (const float*)d_in[10];
    const float* bhh1 = (const float*)d_in[11];
    const float* Wih2 = (const float*)d_in[12];
    const float* Whh2 = (const float*)d_in[13];
    const float* bih2 = (const float*)d_in[14];
    const float* bhh2 = (const float*)d_in[15];
    const float* Wl   = (const float*)d_in[16];
    const float* bl   = (const float*)d_in[17];
    float* out = (float*)d_out;

    __nv_bfloat16 *p_tagsb, *p_Wtag, *p_Wcomb, *p_Wlb, *p_hb, *p_prevb;
    float *p_tb, *p_c, *p_bI;
    cudaGetSymbolAddress((void**)&p_tagsb, g_tagsb);
    cudaGetSymbolAddress((void**)&p_Wtag,  g_Wtag);
    cudaGetSymbolAddress((void**)&p_Wcomb, g_Wcomb);
    cudaGetSymbolAddress((void**)&p_Wlb,   g_Wlb);
    cudaGetSymbolAddress((void**)&p_hb,    g_hb);
    cudaGetSymbolAddress((void**)&p_prevb, g_prevb);
    cudaGetSymbolAddress((void**)&p_tb,    g_tagbias);
    cudaGetSymbolAddress((void**)&p_c,     g_c);
    cudaGetSymbolAddress((void**)&p_bI,    g_biasI);

    auto hb   = [&](int l, int pp) { return p_hb + ((size_t)l * 2 + pp) * BA; };
    auto prv_ = [&](int pp)        { return p_prevb + (size_t)pp * BA; };

    cudaFuncSetAttribute(gemm_kernel<0>, cudaFuncAttributeMaxDynamicSharedMemorySize, SMEMB);
    cudaFuncSetAttribute(gemm_kernel<1>, cudaFuncAttributeMaxDynamicSharedMemorySize, SMEMB);
    cudaFuncSetAttribute(gemm_kernel<2>, cudaFuncAttributeMaxDynamicSharedMemorySize, SMEMB);

    const dim3 gridFull(G4 / TN, Bsz / TM);   // (16, 16) = 256 CTAs (2/SM)
    const dim3 gridHead(Asz / TN, Bsz / TM);  // (4, 16)  = 64 CTAs

    // 1) prep
    prep_kernel<<<1024, 256>>>(tags, Wih0, Whh0, bih0, bhh0,
                               Wih1, Whh1, bih1, bhh1,
                               Wih2, Whh2, bih2, bhh2, Wl, out);

    // 2) tagbias = tags @ Wtag^T + biasI[0]
    gemm_kernel<0><<<gridFull, NT, SMEMB>>>(p_tagsb, Tsz, Tsz, nullptr,
                                            p_Wtag, Tsz,
                                            p_bI, nullptr,
                                            p_tb, nullptr, nullptr, nullptr, nullptr);

    // 3) 49 recurrent steps
    for (int t = 1; t < Lsz; t++) {
        const int cur = t & 1, prv = cur ^ 1;

        gemm_kernel<1><<<gridFull, NT, SMEMB>>>(prv_(prv), Asz, Asz, hb(0, prv),
                                                p_Wcomb + 0 * (size_t)G4 * 768, 768,
                                                nullptr, p_tb,
                                                nullptr, hb(0, cur), p_c + 0 * BA,
                                                nullptr, nullptr);

        gemm_kernel<1><<<gridFull, NT, SMEMB>>>(hb(0, cur), Asz, Asz, hb(1, prv),
                                                p_Wcomb + 1 * (size_t)G4 * 768, 768,
                                                p_bI + G4, nullptr,
                                                nullptr, hb(1, cur), p_c + 1 * BA,
                                                nullptr, nullptr);

        gemm_kernel<1><<<gridFull, NT, SMEMB>>>(hb(1, cur), Asz, Asz, hb(2, prv),
                                                p_Wcomb + 2 * (size_t)G4 * 768, 768,
                                                p_bI + 2 * G4, nullptr,
                                                nullptr, hb(2, cur), p_c + 2 * BA,
                                                nullptr, nullptr);

        gemm_kernel<2><<<gridHead, NT, SMEMB>>>(hb(2, cur), Asz, Asz, nullptr,
                                                p_Wlb, Asz,
                                                bl, nullptr,
                                                nullptr, nullptr, nullptr,
                                                prv_(cur), out + (size_t)t * Asz);
    }
}